// round 3
// baseline (speedup 1.0000x reference)
#include <cuda_runtime.h>
#include <cstdint>
#include <cstddef>

// Problem constants
#define NROWS 65536   // 64*32*32 flat rows
#define KC    1024    // codes
#define DIM   256     // embedding dim
#define HW    1024    // 32*32
#define BATCH 64

// Output packing (tuple order, all float32)
#define OUT_ZQ   0ull
#define OUT_LOSS 16777216ull
#define OUT_IDX  16777217ull
#define OUT_CB   16842753ull
#define OUT_CS   17104897ull
#define OUT_DW   17105921ull

// Scratch (device globals: no allocations allowed)
__device__ float  g_c2[KC];
__device__ float  g_f2[NROWS];
__device__ int    g_idx[NROWS];
__device__ int    g_counts[KC];
__device__ float  g_dw[KC * DIM];
__device__ double g_loss;
__device__ int    g_rand[KC];
__device__ float  g_smooth[KC];
__device__ int    g_dead[KC];

// ---------------------------------------------------------------------------
__global__ void k_init() {
    int i = blockIdx.x * blockDim.x + threadIdx.x;
    if (i < KC * DIM) g_dw[i] = 0.0f;
    if (i < KC)       g_counts[i] = 0;
    if (i == 0)       g_loss = 0.0;
}

// ---------------------------------------------------------------------------
// c2[k] = sum_d fl(cb[k][d]^2), sequential in-order fp32 (XLA CPU naive reduce)
__global__ void k_c2(const float* __restrict__ cb) {
    int k = blockIdx.x * blockDim.x + threadIdx.x;
    if (k >= KC) return;
    const float* row = cb + (size_t)k * DIM;
    float s = 0.0f;
    for (int d = 0; d < DIM; ++d) {
        float v = row[d];
        s = __fadd_rn(s, __fmul_rn(v, v));
    }
    g_c2[k] = s;
}

// ---------------------------------------------------------------------------
__global__ void __launch_bounds__(256) k_f2(const float* __restrict__ z) {
    int n = blockIdx.x * 256 + threadIdx.x;
    int b = n >> 10, hw = n & 1023;
    const float* p = z + (size_t)b * DIM * HW + hw;
    float acc = 0.0f;
#pragma unroll 8
    for (int d = 0; d < DIM; ++d) {
        float v = p[(size_t)d * HW];
        acc = __fadd_rn(acc, __fmul_rn(v, v));
    }
    g_f2[n] = acc;
}

// ---------------------------------------------------------------------------
// Exact JAX threefry2x32 for key(1)
__device__ __forceinline__ uint32_t tf_rotl(uint32_t v, int r) {
    return (v << r) | (v >> (32 - r));
}
__global__ void k_rng() {
    int i = threadIdx.x;
    if (i >= 512) return;
    const uint32_t ks0 = 0u, ks1 = 1u, ks2 = 0x1BD11BDBu;
    uint32_t x0 = (uint32_t)i + ks0;
    uint32_t x1 = (uint32_t)(i + 512) + ks1;
    const int ra[4] = {13, 15, 26, 6};
    const int rb[4] = {17, 29, 16, 24};
#define TF_R4(rots) { x0 += x1; x1 = tf_rotl(x1, rots[0]); x1 ^= x0; \
                      x0 += x1; x1 = tf_rotl(x1, rots[1]); x1 ^= x0; \
                      x0 += x1; x1 = tf_rotl(x1, rots[2]); x1 ^= x0; \
                      x0 += x1; x1 = tf_rotl(x1, rots[3]); x1 ^= x0; }
    TF_R4(ra); x0 += ks1; x1 += ks2 + 1u;
    TF_R4(rb); x0 += ks2; x1 += ks0 + 2u;
    TF_R4(ra); x0 += ks0; x1 += ks1 + 3u;
    TF_R4(rb); x0 += ks1; x1 += ks2 + 4u;
    TF_R4(ra); x0 += ks2; x1 += ks0 + 5u;
#undef TF_R4
    g_rand[i]       = (int)(x0 & 0xFFFFu);
    g_rand[i + 512] = (int)(x1 & 0xFFFFu);
}

// ---------------------------------------------------------------------------
// Packed fp32x2 FMA: per-lane IEEE fp32 fma -> bitwise identical to scalar
// chain. lo lane = even code, hi lane = odd code.
__device__ __forceinline__ void ffma2(unsigned long long& acc,
                                      unsigned long long a,
                                      unsigned long long b) {
    asm("fma.rn.f32x2 %0, %1, %2, %0;" : "+l"(acc) : "l"(a), "l"(b));
}

// smem: s_fd (row-dup) float4[128][64] = 128KB, then s_cp float4[128][32] = 64KB
#define SMEM_ARGMIN (131072 + 65536)

__global__ void __launch_bounds__(256) k_argmin(const float* __restrict__ z,
                                                const float* __restrict__ cb) {
    extern __shared__ float sm[];
    float4* s_fd4 = (float4*)sm;                 // [d2][r]: {f,f,f',f'}
    float*  s_cf  = sm + 4 * 128 * 64;           // code tile floats
    float4* s_cp4 = (float4*)s_cf;               // [d2][j^]: {cE,cO,cE',cO'}

    const int tid = threadIdx.x;
    const int n0  = blockIdx.x * 64;
    const int b   = n0 >> 10;
    const int hw0 = n0 & 1023;
    const float* zb = z + (size_t)b * DIM * HW + hw0;

    // ---- load flat tile, duplicated pairs: s_fd[d>>1][r] comp (d&1)*2..+1
    {
        int r = tid & 63;
        int dbase = tid >> 6;                    // 0..3
#pragma unroll
        for (int i = 0; i < 64; ++i) {
            int d = i * 4 + dbase;
            float v = zb[(size_t)d * HW + r];
            int fidx = ((d >> 1) * 64 + r) * 4 + (d & 1) * 2;
            *(float2*)(sm + fidx) = make_float2(v, v);
        }
    }
    __syncthreads();

    const int g = tid & 15;        // code-group: codes 4g..4g+3 in tile
    const int q = tid >> 4;        // row-group : rows 4q..4q+3

    float4 f2v = *(const float4*)&g_f2[n0 + 4 * q];
    const float f2a[4] = {f2v.x, f2v.y, f2v.z, f2v.w};

    float best[4];
    int   bk[4];
#pragma unroll
    for (int a = 0; a < 4; ++a) { best[a] = 3.4e38f; bk[a] = 0; }

    const float4* fd_base = s_fd4 + 4 * q;

    for (int t = 0; t < 16; ++t) {
        __syncthreads();
        // ---- stage 64-code tile into pair-packed swizzled layout
        {
            const float* cbt = cb + (size_t)(t * 64) * DIM;
            int d  = tid;
            int d2 = d >> 1, h = d & 1;
            int sw = d2 & 7;
            int base = d2 * 128 + h * 2;         // float index base (f4s*4 + h*2)
#pragma unroll
            for (int i = 0; i < 64; ++i) {
                float v = cbt[i * 256 + d];
                int j = i >> 1, cl = i & 1;
                s_cf[base + ((j ^ sw) << 2) + cl] = v;
            }
        }
        __syncthreads();

        unsigned long long acc[4][2];
#pragma unroll
        for (int a = 0; a < 4; ++a) { acc[a][0] = 0ull; acc[a][1] = 0ull; }

        for (int d2b = 0; d2b < 128; d2b += 8) {
#pragma unroll
            for (int u = 0; u < 8; ++u) {
                const int d2 = d2b + u;          // d2 & 7 == u
                const float4* fd = fd_base + d2 * 64;
                ulonglong2 r0 = *(const ulonglong2*)(fd + 0);
                ulonglong2 r1 = *(const ulonglong2*)(fd + 1);
                ulonglong2 r2 = *(const ulonglong2*)(fd + 2);
                ulonglong2 r3 = *(const ulonglong2*)(fd + 3);
                const float4* cp = s_cp4 + d2 * 32;
                ulonglong2 c0 = *(const ulonglong2*)(cp + ((2 * g)     ^ u));
                ulonglong2 c1 = *(const ulonglong2*)(cp + ((2 * g + 1) ^ u));
                // dim d then d+1, sequential per accumulator (bitwise order)
                ffma2(acc[0][0], r0.x, c0.x); ffma2(acc[0][0], r0.y, c0.y);
                ffma2(acc[0][1], r0.x, c1.x); ffma2(acc[0][1], r0.y, c1.y);
                ffma2(acc[1][0], r1.x, c0.x); ffma2(acc[1][0], r1.y, c0.y);
                ffma2(acc[1][1], r1.x, c1.x); ffma2(acc[1][1], r1.y, c1.y);
                ffma2(acc[2][0], r2.x, c0.x); ffma2(acc[2][0], r2.y, c0.y);
                ffma2(acc[2][1], r2.x, c1.x); ffma2(acc[2][1], r2.y, c1.y);
                ffma2(acc[3][0], r3.x, c0.x); ffma2(acc[3][0], r3.y, c0.y);
                ffma2(acc[3][1], r3.x, c1.x); ffma2(acc[3][1], r3.y, c1.y);
            }
        }

        // ---- epilogue: d2 = fl(fl(f2 - 2r) + c2), ties -> lowest k
        int kb = t * 64 + 4 * g;
        float4 c2t = *(const float4*)&g_c2[kb];
#pragma unroll
        for (int a = 0; a < 4; ++a) {
            float rA = __uint_as_float((unsigned)(acc[a][0]));
            float rB = __uint_as_float((unsigned)(acc[a][0] >> 32));
            float rC = __uint_as_float((unsigned)(acc[a][1]));
            float rD = __uint_as_float((unsigned)(acc[a][1] >> 32));
            float dA = __fadd_rn(__fsub_rn(f2a[a], 2.0f * rA), c2t.x);
            float dB = __fadd_rn(__fsub_rn(f2a[a], 2.0f * rB), c2t.y);
            float dC = __fadd_rn(__fsub_rn(f2a[a], 2.0f * rC), c2t.z);
            float dD = __fadd_rn(__fsub_rn(f2a[a], 2.0f * rD), c2t.w);
            if (dA < best[a]) { best[a] = dA; bk[a] = kb; }
            if (dB < best[a]) { best[a] = dB; bk[a] = kb + 1; }
            if (dC < best[a]) { best[a] = dC; bk[a] = kb + 2; }
            if (dD < best[a]) { best[a] = dD; bk[a] = kb + 3; }
        }
    }

    // ---- reduce across the 16 code-groups sharing a row-set (lanes of same q)
#pragma unroll
    for (int a = 0; a < 4; ++a) {
#pragma unroll
        for (int off = 1; off < 16; off <<= 1) {
            float ov = __shfl_xor_sync(0xffffffffu, best[a], off);
            int   ok = __shfl_xor_sync(0xffffffffu, bk[a],   off);
            if (ov < best[a] || (ov == best[a] && ok < bk[a])) {
                best[a] = ov; bk[a] = ok;
            }
        }
    }
    if (g == 0) {
#pragma unroll
        for (int a = 0; a < 4; ++a) {
            g_idx[n0 + 4 * q + a] = bk[a];
            atomicAdd(&g_counts[bk[a]], 1);
        }
    }
}

// ---------------------------------------------------------------------------
__global__ void __launch_bounds__(256) k_scatter(const float* __restrict__ z,
                                                 const float* __restrict__ cb,
                                                 float* __restrict__ out,
                                                 size_t osz) {
    int n  = blockIdx.x * 256 + threadIdx.x;
    int b  = n >> 10, hw = n & 1023;
    int k  = g_idx[n];
    if (OUT_IDX + (size_t)n < osz) out[OUT_IDX + n] = (float)k;

    const float*  zr   = z  + (size_t)b * DIM * HW + hw;
    float*        orow = out + OUT_ZQ + (size_t)b * DIM * HW + hw;
    const float4* cr   = (const float4*)(cb + (size_t)k * DIM);
    float*        dwr  = g_dw + (size_t)k * DIM;

    float ls = 0.0f;
#pragma unroll 4
    for (int d4 = 0; d4 < 64; ++d4) {
        float4 qv = cr[d4];
        int d = d4 * 4;
        float z0 = zr[(size_t)(d + 0) * HW];
        float z1 = zr[(size_t)(d + 1) * HW];
        float z2 = zr[(size_t)(d + 2) * HW];
        float z3 = zr[(size_t)(d + 3) * HW];
        orow[(size_t)(d + 0) * HW] = qv.x;
        orow[(size_t)(d + 1) * HW] = qv.y;
        orow[(size_t)(d + 2) * HW] = qv.z;
        orow[(size_t)(d + 3) * HW] = qv.w;
        float e0 = qv.x - z0, e1 = qv.y - z1, e2 = qv.z - z2, e3 = qv.w - z3;
        ls = fmaf(e0, e0, ls); ls = fmaf(e1, e1, ls);
        ls = fmaf(e2, e2, ls); ls = fmaf(e3, e3, ls);
        atomicAdd(&dwr[d + 0], z0);
        atomicAdd(&dwr[d + 1], z1);
        atomicAdd(&dwr[d + 2], z2);
        atomicAdd(&dwr[d + 3], z3);
    }

    for (int o = 16; o > 0; o >>= 1) ls += __shfl_down_sync(0xffffffffu, ls, o);
    __shared__ float ws[8];
    int lane = threadIdx.x & 31, w = threadIdx.x >> 5;
    if (lane == 0) ws[w] = ls;
    __syncthreads();
    if (threadIdx.x == 0) {
        float s = 0.0f;
#pragma unroll
        for (int i = 0; i < 8; ++i) s += ws[i];
        atomicAdd(&g_loss, (double)s);
    }
}

// ---------------------------------------------------------------------------
__global__ void k_fin_a(const float* __restrict__ ema_cs,
                        float* __restrict__ out, size_t osz) {
    int k = threadIdx.x;
    float cs = __fadd_rn(__fmul_rn(0.99f, ema_cs[k]),
                         __fmul_rn(0.01f, (float)g_counts[k]));
    __shared__ float red[1024];
    red[k] = cs;
    __syncthreads();
    for (int o = 512; o > 0; o >>= 1) {
        if (k < o) red[k] += red[k + o];
        __syncthreads();
    }
    float n = red[0];
    float smv = (cs + 1e-5f) / (n + 1024.0f * 1e-5f) * n;
    g_smooth[k] = smv;
    int dead = cs < 1.0f;
    g_dead[k] = dead;
    if (OUT_CS + (size_t)k < osz) out[OUT_CS + k] = dead ? 1.0f : cs;
    if (k == 0 && OUT_LOSS < osz)
        out[OUT_LOSS] = (float)(0.5 * g_loss / 16777216.0);
}

// ---------------------------------------------------------------------------
__global__ void k_fin_b(const float* __restrict__ ema_dw,
                        const float* __restrict__ z,
                        float* __restrict__ out, size_t osz) {
    int k = blockIdx.x;
    int d = threadIdx.x;
    size_t e = (size_t)k * DIM + d;
    float dwe = __fadd_rn(__fmul_rn(0.99f, ema_dw[e]),
                          __fmul_rn(0.01f, g_dw[e]));
    float cbv = dwe / g_smooth[k];
    if (g_dead[k]) {
        int r = g_rand[k];
        int rb = r >> 10, rhw = r & 1023;
        float rr = z[((size_t)rb * DIM + d) * HW + rhw];
        cbv = rr;
        dwe = rr;
    }
    if (OUT_CB + e < osz) out[OUT_CB + e] = cbv;
    if (OUT_DW + e < osz) out[OUT_DW + e] = dwe;
}

// ---------------------------------------------------------------------------
extern "C" void kernel_launch(void* const* d_in, const int* in_sizes, int n_in,
                              void* d_out, int out_size) {
    const float* z      = (const float*)d_in[0];
    const float* cb     = (const float*)d_in[1];
    const float* ema_cs = (const float*)d_in[2];
    const float* ema_dw = (const float*)d_in[3];
    float* out = (float*)d_out;
    size_t osz = (size_t)out_size;

    cudaFuncSetAttribute(k_argmin, cudaFuncAttributeMaxDynamicSharedMemorySize,
                         SMEM_ARGMIN);

    k_init<<<1024, 256>>>();
    k_c2<<<4, 256>>>(cb);
    k_f2<<<256, 256>>>(z);
    k_rng<<<1, 512>>>();
    k_argmin<<<1024, 256, SMEM_ARGMIN>>>(z, cb);
    k_scatter<<<256, 256>>>(z, cb, out, osz);
    k_fin_a<<<1, 1024>>>(ema_cs, out, osz);
    k_fin_b<<<1024, 256>>>(ema_dw, z, out, osz);
}